// round 6
// baseline (speedup 1.0000x reference)
#include <cuda_runtime.h>
#include <cuda_bf16.h>
#include <cstdint>

// depth[t] = dot(patches[t], W_tok @ W_depth)
//          + dot(coords[t],  W_pos @ W_depth)
//          + (b_tok + b_pos) . W_depth + b_depth
// Kernel 1: fold weights (one warp per row, coalesced).
// Kernel 2: persistent TMA-pipelined streamer. Producer warp bulk-copies
//           16-token (48 KB) tiles into a 3-stage SMEM ring; 16 consumer
//           warps each reduce one token per tile with register-resident v_tok.

#define PATCH_DIM 768
#define EMBED_DIM 256

#define TOKENS_PER_TILE 16
#define TILE_BYTES (TOKENS_PER_TILE * PATCH_DIM * 4)   // 49152
#define STAGES 3
#define CONS_THREADS 512                                // 16 consumer warps
#define THREADS 544                                     // + 1 producer warp

__device__ float g_vtok[PATCH_DIM];
__device__ float g_vpos[3];
__device__ float g_bias;

// ---------------- fold ----------------
__global__ void fold_weights_kernel(const float* __restrict__ W_tok,
                                    const float* __restrict__ b_tok,
                                    const float* __restrict__ W_pos,
                                    const float* __restrict__ b_pos,
                                    const float* __restrict__ W_dep,
                                    const float* __restrict__ b_dep) {
    int warp = (int)((blockIdx.x * blockDim.x + threadIdx.x) >> 5);
    int lane = threadIdx.x & 31;

    if (warp < PATCH_DIM) {
        const float* row = W_tok + (size_t)warp * EMBED_DIM;
        float s = 0.f;
        #pragma unroll
        for (int j = 0; j < EMBED_DIM / 32; ++j)
            s = fmaf(row[lane + 32 * j], W_dep[lane + 32 * j], s);
        #pragma unroll
        for (int off = 16; off > 0; off >>= 1)
            s += __shfl_xor_sync(0xffffffffu, s, off);
        if (lane == 0) g_vtok[warp] = s;
    } else if (warp < PATCH_DIM + 3) {
        int r = warp - PATCH_DIM;
        const float* row = W_pos + (size_t)r * EMBED_DIM;
        float s = 0.f;
        #pragma unroll
        for (int j = 0; j < EMBED_DIM / 32; ++j)
            s = fmaf(row[lane + 32 * j], W_dep[lane + 32 * j], s);
        #pragma unroll
        for (int off = 16; off > 0; off >>= 1)
            s += __shfl_xor_sync(0xffffffffu, s, off);
        if (lane == 0) g_vpos[r] = s;
    } else if (warp == PATCH_DIM + 3) {
        float s = 0.f;
        #pragma unroll
        for (int j = 0; j < EMBED_DIM / 32; ++j) {
            int e = lane + 32 * j;
            s = fmaf(b_tok[e] + b_pos[e], W_dep[e], s);
        }
        #pragma unroll
        for (int off = 16; off > 0; off >>= 1)
            s += __shfl_xor_sync(0xffffffffu, s, off);
        if (lane == 0) g_bias = s + b_dep[0];
    }
}

// ---------------- mbarrier / TMA helpers ----------------
__device__ __forceinline__ uint32_t smem_u32(const void* p) {
    uint32_t a;
    asm("{ .reg .u64 t; cvta.to.shared.u64 t, %1; cvt.u32.u64 %0, t; }"
        : "=r"(a) : "l"(p));
    return a;
}
__device__ __forceinline__ void mbar_init(uint32_t mbar, uint32_t count) {
    asm volatile("mbarrier.init.shared.b64 [%0], %1;" :: "r"(mbar), "r"(count) : "memory");
}
__device__ __forceinline__ void mbar_expect_tx(uint32_t mbar, uint32_t bytes) {
    asm volatile("mbarrier.arrive.expect_tx.shared.b64 _, [%0], %1;"
                 :: "r"(mbar), "r"(bytes) : "memory");
}
__device__ __forceinline__ void mbar_arrive(uint32_t mbar) {
    asm volatile("mbarrier.arrive.shared.b64 _, [%0];" :: "r"(mbar) : "memory");
}
__device__ __forceinline__ void mbar_wait(uint32_t mbar, uint32_t parity) {
    uint32_t done;
    asm volatile(
        "{\n\t.reg .pred p;\n\t"
        "mbarrier.try_wait.parity.acquire.cta.shared::cta.b64 p, [%1], %2;\n\t"
        "selp.b32 %0, 1, 0, p;\n\t}"
        : "=r"(done) : "r"(mbar), "r"(parity) : "memory");
    if (!done) {
        asm volatile(
            "{\n\t.reg .pred P1;\n\t"
            "W_%=:\n\t"
            "mbarrier.try_wait.parity.acquire.cta.shared::cta.b64 P1, [%0], %1, 0x989680;\n\t"
            "@P1 bra.uni D_%=;\n\t"
            "bra.uni W_%=;\n\t"
            "D_%=:\n\t}"
            :: "r"(mbar), "r"(parity) : "memory");
    }
}
__device__ __forceinline__ void bulk_g2s(uint32_t dst_smem, const void* src_gmem,
                                         uint32_t bytes, uint32_t mbar) {
    asm volatile(
        "cp.async.bulk.shared::cluster.global.mbarrier::complete_tx::bytes "
        "[%0], [%1], %2, [%3];"
        :: "r"(dst_smem), "l"(src_gmem), "r"(bytes), "r"(mbar) : "memory");
}

// ---------------- streamer ----------------
__global__ __launch_bounds__(THREADS, 1)
void depth_kernel(const float* __restrict__ patches,
                  const float* __restrict__ coords,
                  float* __restrict__ out,
                  int T, int numTiles) {
    extern __shared__ __align__(128) char smem[];
    __shared__ uint64_t bars[2 * STAGES];   // [full0, empty0, full1, ...]

    int tid  = threadIdx.x;
    int wid  = tid >> 5;
    int lane = tid & 31;

    uint32_t bar0 = smem_u32(&bars[0]);
    auto full_bar  = [&](int s) { return bar0 + (uint32_t)(2 * s) * 8u; };
    auto empty_bar = [&](int s) { return bar0 + (uint32_t)(2 * s + 1) * 8u; };

    if (tid == 0) {
        #pragma unroll
        for (int s = 0; s < STAGES; ++s) {
            mbar_init(full_bar(s), 1);
            mbar_init(empty_bar(s), CONS_THREADS);
        }
        // order mbarrier.init before any async use (producer TMA / waits)
        asm volatile("fence.proxy.async.shared::cta;" ::: "memory");
    }
    __syncthreads();

    if (wid == 16) {
        // ---- producer warp (lane 0 only) ----
        if (lane == 0) {
            for (int i = 0;; ++i) {
                int tile = blockIdx.x + i * gridDim.x;
                if (tile >= numTiles) break;
                int s = i % STAGES;
                int k = i / STAGES;
                if (k > 0) mbar_wait(empty_bar(s), (uint32_t)((k - 1) & 1));
                int base = tile * TOKENS_PER_TILE;
                int ntok = T - base;
                if (ntok > TOKENS_PER_TILE) ntok = TOKENS_PER_TILE;
                uint32_t bytes = (uint32_t)ntok * PATCH_DIM * 4u;
                mbar_expect_tx(full_bar(s), bytes);
                bulk_g2s(smem_u32(smem) + (uint32_t)s * TILE_BYTES,
                         patches + (size_t)base * PATCH_DIM, bytes, full_bar(s));
            }
        }
        return;
    }

    // ---- consumer warps 0..15: one token per tile each ----
    const float4* v4 = (const float4*)g_vtok;
    float4 v0 = v4[lane +   0], v1 = v4[lane +  32], v2 = v4[lane +  64];
    float4 v3 = v4[lane +  96], v4r = v4[lane + 128], v5 = v4[lane + 160];
    float vp0 = g_vpos[0], vp1 = g_vpos[1], vp2 = g_vpos[2], bias = g_bias;

    for (int i = 0;; ++i) {
        int tile = blockIdx.x + i * gridDim.x;
        if (tile >= numTiles) break;
        int s = i % STAGES;
        int k = i / STAGES;
        mbar_wait(full_bar(s), (uint32_t)(k & 1));

        int tok = tile * TOKENS_PER_TILE + wid;
        if (tok < T) {
            const float4* row = (const float4*)(smem + (size_t)s * TILE_BYTES
                                                     + (size_t)wid * (PATCH_DIM * 4));
            float4 a0 = row[lane +   0], a1 = row[lane +  32], a2 = row[lane +  64];
            float4 a3 = row[lane +  96], a4 = row[lane + 128], a5 = row[lane + 160];

            float s0 = 0.f, s1 = 0.f;
            s0 = fmaf(a0.x, v0.x, s0);  s1 = fmaf(a0.y, v0.y, s1);
            s0 = fmaf(a0.z, v0.z, s0);  s1 = fmaf(a0.w, v0.w, s1);
            s0 = fmaf(a1.x, v1.x, s0);  s1 = fmaf(a1.y, v1.y, s1);
            s0 = fmaf(a1.z, v1.z, s0);  s1 = fmaf(a1.w, v1.w, s1);
            s0 = fmaf(a2.x, v2.x, s0);  s1 = fmaf(a2.y, v2.y, s1);
            s0 = fmaf(a2.z, v2.z, s0);  s1 = fmaf(a2.w, v2.w, s1);
            s0 = fmaf(a3.x, v3.x, s0);  s1 = fmaf(a3.y, v3.y, s1);
            s0 = fmaf(a3.z, v3.z, s0);  s1 = fmaf(a3.w, v3.w, s1);
            s0 = fmaf(a4.x, v4r.x, s0); s1 = fmaf(a4.y, v4r.y, s1);
            s0 = fmaf(a4.z, v4r.z, s0); s1 = fmaf(a4.w, v4r.w, s1);
            s0 = fmaf(a5.x, v5.x, s0);  s1 = fmaf(a5.y, v5.y, s1);
            s0 = fmaf(a5.z, v5.z, s0);  s1 = fmaf(a5.w, v5.w, s1);
            float sum = s0 + s1;

            #pragma unroll
            for (int off = 16; off > 0; off >>= 1)
                sum += __shfl_xor_sync(0xffffffffu, sum, off);

            if (lane == 0) {
                const float* c3 = coords + 3 * (size_t)tok;
                out[tok] = sum + c3[0] * vp0 + c3[1] * vp1 + c3[2] * vp2 + bias;
            }
        }
        mbar_arrive(empty_bar(s));   // per-thread arrive (512 total)
    }
}

extern "C" void kernel_launch(void* const* d_in, const int* in_sizes, int n_in,
                              void* d_out, int out_size) {
    const float* coords  = (const float*)d_in[1];
    const float* patches = (const float*)d_in[2];
    const float* W_tok   = (const float*)d_in[3];
    const float* b_tok   = (const float*)d_in[4];
    const float* W_pos   = (const float*)d_in[5];
    const float* b_pos   = (const float*)d_in[6];
    const float* W_dep   = (const float*)d_in[7];
    const float* b_dep   = (const float*)d_in[8];
    float* out = (float*)d_out;

    int T = in_sizes[2] / PATCH_DIM;
    int numTiles = (T + TOKENS_PER_TILE - 1) / TOKENS_PER_TILE;

    fold_weights_kernel<<<97, 256>>>(W_tok, b_tok, W_pos, b_pos, W_dep, b_dep);

    // No static guard (harness rule): idempotent, not a stream op, capture-safe.
    cudaFuncSetAttribute(depth_kernel,
                         cudaFuncAttributeMaxDynamicSharedMemorySize,
                         STAGES * TILE_BYTES);

    int blocks = 148;
    if (blocks > numTiles) blocks = numTiles;
    depth_kernel<<<blocks, THREADS, STAGES * TILE_BYTES>>>(
        patches, coords, out, T, numTiles);
}